// round 9
// baseline (speedup 1.0000x reference)
#include <cuda_runtime.h>
#include <cstdint>

#define S_    512
#define P_    196
#define Q_    48
#define CB_   8
#define R_    32
#define C_    10
#define NMID  6

#define THREADS 512

// shared memory layout (floats) — sx and sG SHARE region [0, 9408); x reloaded per step
#define OFF_X   0                      // 9408   x[p][q]   (destroyed by G each step)
#define OFF_G   0                      // 8192   G tile [ab(64)][col(128)] col = l_loc*32+r
#define OFF_M   9408                   // 12544  M[p][ab]
#define OFF_ST  21952                  // 2*2560 state[a*320 + l*10 + c]
#define OFF_OUT 27072                  // 16
#define SMEM_FLOATS 27088

// M row stride in ulonglong2 units: 64 floats = 16 ulonglong2
#define MSTRIDE 16

__device__ __forceinline__ void ffma2(uint64_t& d, uint64_t a, uint64_t b) {
    asm("fma.rn.f32x2 %0, %1, %2, %0;" : "+l"(d) : "l"(a), "l"(b));
}
__device__ __forceinline__ uint64_t bcast2(float v) {
    uint64_t r; unsigned u = __float_as_uint(v);
    asm("mov.b64 %0, {%1, %1};" : "=l"(r) : "r"(u));
    return r;
}
__device__ __forceinline__ float2 unpack2(uint64_t v) {
    float2 f;
    asm("mov.b64 {%0, %1}, %2;" : "=f"(f.x), "=f"(f.y) : "l"(v));
    return f;
}

// 8 packed-FMA2: 8 rows (ma=rows0-3, mb=rows4-7 as u64 pairs) x 2 cols (av.x, av.y)
#define FFMA2_BLK8(ACC, MA, MB, AV)                                   \
    {                                                                 \
        uint64_t b0 = bcast2(AV.x), b1 = bcast2(AV.y);                \
        ffma2(ACC[0], MA.x, b0); ffma2(ACC[1], MA.x, b1);             \
        ffma2(ACC[2], MA.y, b0); ffma2(ACC[3], MA.y, b1);             \
        ffma2(ACC[4], MB.x, b0); ffma2(ACC[5], MB.x, b1);             \
        ffma2(ACC[6], MB.y, b0); ffma2(ACC[7], MB.y, b1);             \
    }

__global__ void __launch_bounds__(THREADS, 2)
tctl_kernel(const float* __restrict__ x,
            const float* __restrict__ cf,   // [Q][CB]
            const float* __restrict__ cm,   // [NMID][CB][Q][CB]
            const float* __restrict__ cl,   // [CB][Q]
            const float* __restrict__ tf,   // [C][P][R]
            const float* __restrict__ tm,   // [NMID][R][P][R]
            const float* __restrict__ tl,   // [R][P]
            float* __restrict__ out)        // [S][C]
{
    extern __shared__ float smem[];
    float* sx     = smem + OFF_X;
    float* sG     = smem + OFF_G;
    float* sM     = smem + OFF_M;
    float* sState = smem + OFF_ST;
    float* sOut   = smem + OFF_OUT;

    const int tid = threadIdx.x;
    const int s   = blockIdx.x;
    const float4* xg = (const float4*)(x + (size_t)s * (P_ * Q_));

    // ---------- load x sample ----------
    {
        float4* sx4 = (float4*)sx;
        for (int i = tid; i < (P_ * Q_) / 4; i += THREADS) sx4[i] = xg[i];
    }
    __syncthreads();

    // ---------- carriage 1: y1[p,b] = sum_q x[p,q] cf[q,b] (into sM[p*8+b]) ----------
    for (int e = tid; e < P_ * CB_; e += THREADS) {
        int p = e >> 3, b = e & 7;
        const float* xp = sx + p * Q_;
        float acc = 0.f;
        #pragma unroll
        for (int q = 0; q < Q_; q++) acc += xp[q] * cf[q * 8 + b];
        sM[e] = acc;
    }
    __syncthreads();

    // state0[b,r,c] = sum_p y1[p,b] * tf[c,p,r]   (threads 0..255)
    if (tid < 256) {
        const int b = tid >> 5, r = tid & 31;
        float acc[C_];
        #pragma unroll
        for (int c = 0; c < C_; c++) acc[c] = 0.f;
        for (int p = 0; p < P_; p++) {
            float y = sM[p * 8 + b];
            #pragma unroll
            for (int c = 0; c < C_; c++)
                acc[c] += y * tf[((size_t)c * P_ + p) * R_ + r];
        }
        #pragma unroll
        for (int c = 0; c < C_; c++) sState[b * 320 + r * 10 + c] = acc[c];
    }

    // ---------- mid carriages ----------
    // G mapping: 8 row-groups (8 rows each) x 64 col-groups (2 cols each of 128)
    const int rowGrp = tid >> 6;        // 0..7
    const int colGrp = tid & 63;        // 0..63
    // update mapping: b(8) x r(32) x c-half(2)
    const int bU  = tid >> 6;
    const int rU  = (tid >> 1) & 31;
    const int chU = tid & 1;

    for (int k = 0; k < NMID; k++) {
        const float* Ckg = cm + (size_t)k * (CB_ * Q_ * CB_);
        const float* Ak  = tm + (size_t)k * (R_ * P_ * R_);
        float* stCur = sState + (k & 1) * 2560;
        float* stNxt = sState + ((k & 1) ^ 1) * 2560;

        __syncthreads();  // prev step fully done (incl. update reads of sG region)

        // reload x (sx region was overwritten by G tiles last step; k=0 harmless)
        {
            float4* sx4 = (float4*)sx;
            for (int i = tid; i < (P_ * Q_) / 4; i += THREADS) sx4[i] = xg[i];
        }
        __syncthreads();  // x ready

        // M[p][ab] = sum_q x[p,q] * Ck[a,q,b]; Ck read direct from gmem (L1-hot)
        for (int e4 = tid; e4 < (P_ * 64) / 4; e4 += THREADS) {
            int p  = e4 >> 4;
            int c4 = e4 & 15;
            int a  = c4 >> 1, bq = c4 & 1;
            const float*  xp  = sx + p * Q_;
            const float4* ck4 = (const float4*)(Ckg + a * (Q_ * CB_) + bq * 4);
            float4 acc = make_float4(0.f, 0.f, 0.f, 0.f);
            #pragma unroll
            for (int q = 0; q < Q_; q++) {
                float  f  = xp[q];
                float4 cv = ck4[q * 2];   // stride 8 floats = 2 float4
                acc.x += f * cv.x; acc.y += f * cv.y;
                acc.z += f * cv.z; acc.w += f * cv.w;
            }
            ((float4*)sM)[e4] = acc;
        }

        float ns[5];
        #pragma unroll
        for (int c = 0; c < 5; c++) ns[c] = 0.f;

        // 8 tiles over groups of 4 l-values; G tile [64 rows][4*32 cols]
        for (int lt = 0; lt < 8; lt++) {
            __syncthreads();  // sM ready (lt=0) / prev tile's G reads done

            const int   l   = lt * 4 + (colGrp >> 4);
            const int   r0  = (colGrp & 15) * 2;
            const float* AkL = Ak + (size_t)l * (P_ * R_) + r0;
            const ulonglong2* mbase = ((const ulonglong2*)sM) + rowGrp * 2;

            uint64_t acc[8];
            #pragma unroll
            for (int i = 0; i < 8; i++) acc[i] = 0ull;

            // unroll-2 p loop, av prefetch distance 2; m loaded in-body
            float2 av0 = *(const float2*)(AkL + 0 * R_);
            float2 av1 = *(const float2*)(AkL + 1 * R_);

            #pragma unroll 1
            for (int pb = 0; pb < P_ - 2; pb += 2) {
                float2 avn0 = *(const float2*)(AkL + (pb + 2) * R_);
                ulonglong2 ma0 = mbase[pb * MSTRIDE];
                ulonglong2 mb0 = mbase[pb * MSTRIDE + 1];
                FFMA2_BLK8(acc, ma0, mb0, av0)
                float2 avn1 = *(const float2*)(AkL + (pb + 3) * R_);
                ulonglong2 ma1 = mbase[(pb + 1) * MSTRIDE];
                ulonglong2 mb1 = mbase[(pb + 1) * MSTRIDE + 1];
                FFMA2_BLK8(acc, ma1, mb1, av1)
                av0 = avn0; av1 = avn1;
            }
            // tail: p = 194, 195
            {
                ulonglong2 ma0 = mbase[194 * MSTRIDE];
                ulonglong2 mb0 = mbase[194 * MSTRIDE + 1];
                FFMA2_BLK8(acc, ma0, mb0, av0)
                ulonglong2 ma1 = mbase[195 * MSTRIDE];
                ulonglong2 mb1 = mbase[195 * MSTRIDE + 1];
                FFMA2_BLK8(acc, ma1, mb1, av1)
            }

            // write 8 rows x 2 cols to G (row stride 128 floats = 64 float2)
            float2* g2 = (float2*)sG;
            #pragma unroll
            for (int rp = 0; rp < 4; rp++) {
                float2 c0 = unpack2(acc[rp * 2 + 0]);   // col0: rows rp*2, rp*2+1
                float2 c1 = unpack2(acc[rp * 2 + 1]);   // col1
                g2[(rowGrp * 8 + rp * 2 + 0) * 64 + colGrp] = make_float2(c0.x, c1.x);
                g2[(rowGrp * 8 + rp * 2 + 1) * 64 + colGrp] = make_float2(c0.y, c1.y);
            }
            __syncthreads();  // G tile complete

            // ns[c] += sum_{a,lj} state[a, lt*4+lj, c] * G[a*8+bU, lj*32+rU]
            #pragma unroll
            for (int a = 0; a < CB_; a++) {
                #pragma unroll
                for (int lj = 0; lj < 4; lj++) {
                    float g = sG[(a * 8 + bU) * 128 + lj * 32 + rU];
                    const float* st = stCur + a * 320 + (lt * 4 + lj) * 10 + chU * 5;
                    #pragma unroll
                    for (int c = 0; c < 5; c++) ns[c] += st[c] * g;
                }
            }
        }

        #pragma unroll
        for (int c = 0; c < 5; c++) stNxt[bU * 320 + rU * 10 + chU * 5 + c] = ns[c];
    }

    // ---------- last carriage ----------
    __syncthreads();   // all tile/G reads done

    // reload x (destroyed by final step's G tiles)
    {
        float4* sx4 = (float4*)sx;
        for (int i = tid; i < (P_ * Q_) / 4; i += THREADS) sx4[i] = xg[i];
    }
    __syncthreads();

    // z[p,a] = sum_q x[p,q] cl[a,q]  (into sM[p*8+a])
    for (int e = tid; e < P_ * CB_; e += THREADS) {
        int p = e >> 3, a = e & 7;
        const float* xp  = sx + p * Q_;
        const float* cla = cl + a * Q_;
        float acc = 0.f;
        #pragma unroll
        for (int q = 0; q < Q_; q++) acc += xp[q] * cla[q];
        sM[e] = acc;
    }
    if (tid < C_) sOut[tid] = 0.f;
    __syncthreads();

    // GN[a,l] = sum_p z[p,a] tl[l,p];  out[c] = sum_{a,l} state[a,l,c]*GN[a,l]
    if (tid < 256) {
        const int a = tid >> 5, l = tid & 31;
        const float* tlr = tl + l * P_;
        float gn = 0.f;
        for (int p = 0; p < P_; p++) gn += sM[p * 8 + a] * tlr[p];

        const float* st = sState + /*final buffer 0 (NMID even)*/ a * 320 + l * 10;
        #pragma unroll
        for (int c = 0; c < C_; c++) atomicAdd(&sOut[c], st[c] * gn);
    }
    __syncthreads();

    if (tid < C_) out[(size_t)s * C_ + tid] = sOut[tid];
}

extern "C" void kernel_launch(void* const* d_in, const int* in_sizes, int n_in,
                              void* d_out, int out_size)
{
    const float* x  = (const float*)d_in[0];
    const float* cf = (const float*)d_in[1];
    const float* cm = (const float*)d_in[2];
    const float* cl = (const float*)d_in[3];
    const float* tf = (const float*)d_in[4];
    const float* tm = (const float*)d_in[5];
    const float* tl = (const float*)d_in[6];
    float* out = (float*)d_out;

    size_t shbytes = SMEM_FLOATS * sizeof(float);   // 108352 B -> 2 blocks/SM
    cudaFuncSetAttribute(tctl_kernel, cudaFuncAttributeMaxDynamicSharedMemorySize,
                         (int)shbytes);
    tctl_kernel<<<S_, THREADS, shbytes>>>(x, cf, cm, cl, tf, tm, tl, out);
}

// round 10
// speedup vs baseline: 1.5270x; 1.5270x over previous
#include <cuda_runtime.h>
#include <cstdint>

#define S_    512
#define P_    196
#define Q_    48
#define CB_   8
#define R_    32
#define C_    10
#define NMID  6

#define THREADS 512

// shared memory layout (floats)
#define OFF_X   0                      // 9408   x[p][q]
#define OFF_M   9408                   // 12544  M[p][ab]
#define OFF_G   21952                  // 16384  G tile [ab(64)][col(256)]  col = l_loc*32 + r
#define OFF_CK  38336                  // 3072   Ck as [q][a*8+b]
#define OFF_ST  41408                  // 2*2560 state[a*320 + l*10 + c]
#define OFF_OUT 46528                  // 16
#define SMEM_FLOATS 46544

// M row stride in ulonglong2 units: 64 floats = 16 ulonglong2
#define MSTRIDE 16

__device__ __forceinline__ void ffma2(uint64_t& d, uint64_t a, uint64_t b) {
    asm("fma.rn.f32x2 %0, %1, %2, %0;" : "+l"(d) : "l"(a), "l"(b));
}
__device__ __forceinline__ uint64_t bcast2(float v) {
    uint64_t r; unsigned u = __float_as_uint(v);
    asm("mov.b64 %0, {%1, %1};" : "=l"(r) : "r"(u));
    return r;
}
__device__ __forceinline__ float2 unpack2(uint64_t v) {
    float2 f;
    asm("mov.b64 {%0, %1}, %2;" : "=f"(f.x), "=f"(f.y) : "l"(v));
    return f;
}

// 16 packed-FMA2: 16 rows (M0..M3 = 8 row-pairs) x 2 cols (AV.x, AV.y)
#define FFMA2_16(ACC, M0, M1, M2, M3, AV)                              \
    {                                                                  \
        uint64_t b0 = bcast2(AV.x), b1 = bcast2(AV.y);                 \
        ffma2(ACC[0],  M0.x, b0); ffma2(ACC[1],  M0.x, b1);            \
        ffma2(ACC[2],  M0.y, b0); ffma2(ACC[3],  M0.y, b1);            \
        ffma2(ACC[4],  M1.x, b0); ffma2(ACC[5],  M1.x, b1);            \
        ffma2(ACC[6],  M1.y, b0); ffma2(ACC[7],  M1.y, b1);            \
        ffma2(ACC[8],  M2.x, b0); ffma2(ACC[9],  M2.x, b1);            \
        ffma2(ACC[10], M2.y, b0); ffma2(ACC[11], M2.y, b1);            \
        ffma2(ACC[12], M3.x, b0); ffma2(ACC[13], M3.x, b1);            \
        ffma2(ACC[14], M3.y, b0); ffma2(ACC[15], M3.y, b1);            \
    }

__global__ void __launch_bounds__(THREADS, 1)
tctl_kernel(const float* __restrict__ x,
            const float* __restrict__ cf,   // [Q][CB]
            const float* __restrict__ cm,   // [NMID][CB][Q][CB]
            const float* __restrict__ cl,   // [CB][Q]
            const float* __restrict__ tf,   // [C][P][R]
            const float* __restrict__ tm,   // [NMID][R][P][R]
            const float* __restrict__ tl,   // [R][P]
            float* __restrict__ out)        // [S][C]
{
    extern __shared__ float smem[];
    float* sx     = smem + OFF_X;
    float* sM     = smem + OFF_M;
    float* sG     = smem + OFF_G;
    float* sCk    = smem + OFF_CK;
    float* sState = smem + OFF_ST;
    float* sOut   = smem + OFF_OUT;

    const int tid = threadIdx.x;
    const int s   = blockIdx.x;

    // ---------- load x sample ----------
    {
        const float4* xg = (const float4*)(x + (size_t)s * (P_ * Q_));
        float4* sx4 = (float4*)sx;
        for (int i = tid; i < (P_ * Q_) / 4; i += THREADS) sx4[i] = xg[i];
    }
    for (int i = tid; i < Q_ * CB_; i += THREADS) sCk[i] = cf[i];
    __syncthreads();

    // ---------- carriage 1: y1[p,b] = sum_q x[p,q] cf[q,b] (into sM[p*8+b]) ----------
    for (int e = tid; e < P_ * CB_; e += THREADS) {
        int p = e >> 3, b = e & 7;
        const float* xp = sx + p * Q_;
        float acc = 0.f;
        #pragma unroll
        for (int q = 0; q < Q_; q++) acc += xp[q] * sCk[q * 8 + b];
        sM[e] = acc;
    }
    __syncthreads();

    // state0[b,r,c] = sum_p y1[p,b] * tf[c,p,r]
    if (tid < 256) {
        const int b = tid >> 5, r = tid & 31;
        float acc[C_];
        #pragma unroll
        for (int c = 0; c < C_; c++) acc[c] = 0.f;
        for (int p = 0; p < P_; p++) {
            float y = sM[p * 8 + b];
            #pragma unroll
            for (int c = 0; c < C_; c++)
                acc[c] += y * tf[((size_t)c * P_ + p) * R_ + r];
        }
        #pragma unroll
        for (int c = 0; c < C_; c++) sState[b * 320 + r * 10 + c] = acc[c];
    }

    // ---------- mid carriages ----------
    // G mapping: 4 row-groups (16 rows each) x 128 col-groups (2 cols each of 256)
    const int rowGrp = tid >> 7;        // 0..3   (warp-uniform -> LDS broadcast)
    const int colGrp = tid & 127;       // 0..127
    const int bU  = tid >> 6;
    const int rU  = (tid >> 1) & 31;
    const int chU = tid & 1;

    for (int k = 0; k < NMID; k++) {
        const float* Ck = cm + (size_t)k * (CB_ * Q_ * CB_);
        const float* Ak = tm + (size_t)k * (R_ * P_ * R_);
        float* stCur = sState + (k & 1) * 2560;
        float* stNxt = sState + ((k & 1) ^ 1) * 2560;

        __syncthreads();  // state writes + last step's sM/sG reads done

        // Ck -> sCk as [q][a*8+b]
        for (int i = tid; i < CB_ * Q_ * CB_; i += THREADS) {
            int a  = i / (Q_ * CB_);
            int qb = i % (Q_ * CB_);
            int q = qb >> 3, b = qb & 7;
            sCk[q * 64 + a * 8 + b] = Ck[i];
        }
        __syncthreads();

        // M[p][ab] = sum_q x[p,q] * Ck[a,q,b]
        for (int e4 = tid; e4 < (P_ * 64) / 4; e4 += THREADS) {
            int p  = e4 >> 4;
            int c4 = e4 & 15;
            const float*  xp  = sx + p * Q_;
            const float4* ck4 = ((const float4*)sCk) + c4;
            float4 acc = make_float4(0.f, 0.f, 0.f, 0.f);
            #pragma unroll
            for (int q = 0; q < Q_; q++) {
                float  f  = xp[q];
                float4 cv = ck4[q * 16];
                acc.x += f * cv.x; acc.y += f * cv.y;
                acc.z += f * cv.z; acc.w += f * cv.w;
            }
            ((float4*)sM)[e4] = acc;
        }

        float ns[5];
        #pragma unroll
        for (int c = 0; c < 5; c++) ns[c] = 0.f;

        // 4 tiles over groups of 8 l-values; G tile [64 rows][8*32 cols]
        for (int lt = 0; lt < 4; lt++) {
            __syncthreads();  // sM ready (lt=0) / prev tile's G reads done

            const int   l   = lt * 8 + (colGrp >> 4);
            const int   r0  = (colGrp & 15) * 2;
            const float* AkL = Ak + (size_t)l * (P_ * R_) + r0;
            // this thread's 16 M-rows = 4 ulonglong2 per p (warp-uniform base)
            const ulonglong2* mbase = ((const ulonglong2*)sM) + rowGrp * 4;

            uint64_t acc[16];
            #pragma unroll
            for (int i = 0; i < 16; i++) acc[i] = 0ull;

            // unroll-4 p loop, av (LDG.64) prefetched one full body ahead; m dist-1
            float2 av0 = *(const float2*)(AkL + 0 * R_);
            float2 av1 = *(const float2*)(AkL + 1 * R_);
            float2 av2 = *(const float2*)(AkL + 2 * R_);
            float2 av3 = *(const float2*)(AkL + 3 * R_);
            ulonglong2 m0 = mbase[0], m1 = mbase[1], m2 = mbase[2], m3 = mbase[3];

            #pragma unroll 1
            for (int pb = 0; pb < P_ - 4; pb += 4) {
                float2 avn0 = *(const float2*)(AkL + (pb + 4) * R_);
                ulonglong2 n0 = mbase[(pb + 1) * MSTRIDE + 0];
                ulonglong2 n1 = mbase[(pb + 1) * MSTRIDE + 1];
                ulonglong2 n2 = mbase[(pb + 1) * MSTRIDE + 2];
                ulonglong2 n3 = mbase[(pb + 1) * MSTRIDE + 3];
                FFMA2_16(acc, m0, m1, m2, m3, av0)

                float2 avn1 = *(const float2*)(AkL + (pb + 5) * R_);
                ulonglong2 k0 = mbase[(pb + 2) * MSTRIDE + 0];
                ulonglong2 k1 = mbase[(pb + 2) * MSTRIDE + 1];
                ulonglong2 k2 = mbase[(pb + 2) * MSTRIDE + 2];
                ulonglong2 k3 = mbase[(pb + 2) * MSTRIDE + 3];
                FFMA2_16(acc, n0, n1, n2, n3, av1)

                float2 avn2 = *(const float2*)(AkL + (pb + 6) * R_);
                n0 = mbase[(pb + 3) * MSTRIDE + 0];
                n1 = mbase[(pb + 3) * MSTRIDE + 1];
                n2 = mbase[(pb + 3) * MSTRIDE + 2];
                n3 = mbase[(pb + 3) * MSTRIDE + 3];
                FFMA2_16(acc, k0, k1, k2, k3, av2)

                float2 avn3 = *(const float2*)(AkL + (pb + 7) * R_);
                m0 = mbase[(pb + 4) * MSTRIDE + 0];
                m1 = mbase[(pb + 4) * MSTRIDE + 1];
                m2 = mbase[(pb + 4) * MSTRIDE + 2];
                m3 = mbase[(pb + 4) * MSTRIDE + 3];
                FFMA2_16(acc, n0, n1, n2, n3, av3)

                av0 = avn0; av1 = avn1; av2 = avn2; av3 = avn3;
            }
            // tail: p = 192..195 (av0..av3 loaded; m = row 192)
            {
                ulonglong2 n0 = mbase[193 * MSTRIDE + 0];
                ulonglong2 n1 = mbase[193 * MSTRIDE + 1];
                ulonglong2 n2 = mbase[193 * MSTRIDE + 2];
                ulonglong2 n3 = mbase[193 * MSTRIDE + 3];
                FFMA2_16(acc, m0, m1, m2, m3, av0)
                m0 = mbase[194 * MSTRIDE + 0];
                m1 = mbase[194 * MSTRIDE + 1];
                m2 = mbase[194 * MSTRIDE + 2];
                m3 = mbase[194 * MSTRIDE + 3];
                FFMA2_16(acc, n0, n1, n2, n3, av1)
                n0 = mbase[195 * MSTRIDE + 0];
                n1 = mbase[195 * MSTRIDE + 1];
                n2 = mbase[195 * MSTRIDE + 2];
                n3 = mbase[195 * MSTRIDE + 3];
                FFMA2_16(acc, m0, m1, m2, m3, av2)
                FFMA2_16(acc, n0, n1, n2, n3, av3)
            }

            // write 16 rows x 2 cols to G (row stride 256 floats = 128 float2)
            float2* g2 = (float2*)sG;
            #pragma unroll
            for (int i = 0; i < 8; i++) {
                float2 c0 = unpack2(acc[i * 2 + 0]);
                float2 c1 = unpack2(acc[i * 2 + 1]);
                g2[(rowGrp * 16 + i * 2 + 0) * 128 + colGrp] = make_float2(c0.x, c1.x);
                g2[(rowGrp * 16 + i * 2 + 1) * 128 + colGrp] = make_float2(c0.y, c1.y);
            }
            __syncthreads();  // G tile complete

            // ns[c] += sum_{a,lj} state[a, lt*8+lj, c] * G[a*8+bU, lj*32+rU]
            #pragma unroll
            for (int a = 0; a < CB_; a++) {
                #pragma unroll
                for (int lj = 0; lj < 8; lj++) {
                    float g = sG[(a * 8 + bU) * 256 + lj * 32 + rU];
                    const float* st = stCur + a * 320 + (lt * 8 + lj) * 10 + chU * 5;
                    #pragma unroll
                    for (int c = 0; c < 5; c++) ns[c] += st[c] * g;
                }
            }
        }

        #pragma unroll
        for (int c = 0; c < 5; c++) stNxt[bU * 320 + rU * 10 + chU * 5 + c] = ns[c];
    }

    // ---------- last carriage ----------
    __syncthreads();

    // z[p,a] = sum_q x[p,q] cl[a,q]  (into sM[p*8+a])
    for (int e = tid; e < P_ * CB_; e += THREADS) {
        int p = e >> 3, a = e & 7;
        const float* xp  = sx + p * Q_;
        const float* cla = cl + a * Q_;
        float acc = 0.f;
        #pragma unroll
        for (int q = 0; q < Q_; q++) acc += xp[q] * cla[q];
        sM[e] = acc;
    }
    if (tid < C_) sOut[tid] = 0.f;
    __syncthreads();

    // GN[a,l] = sum_p z[p,a] tl[l,p];  out[c] = sum_{a,l} state[a,l,c]*GN[a,l]
    if (tid < 256) {
        const int a = tid >> 5, l = tid & 31;
        const float* tlr = tl + l * P_;
        float gn = 0.f;
        for (int p = 0; p < P_; p++) gn += sM[p * 8 + a] * tlr[p];

        const float* st = sState + /*final buffer 0 (NMID even)*/ a * 320 + l * 10;
        #pragma unroll
        for (int c = 0; c < C_; c++) atomicAdd(&sOut[c], st[c] * gn);
    }
    __syncthreads();

    if (tid < C_) out[(size_t)s * C_ + tid] = sOut[tid];
}

extern "C" void kernel_launch(void* const* d_in, const int* in_sizes, int n_in,
                              void* d_out, int out_size)
{
    const float* x  = (const float*)d_in[0];
    const float* cf = (const float*)d_in[1];
    const float* cm = (const float*)d_in[2];
    const float* cl = (const float*)d_in[3];
    const float* tf = (const float*)d_in[4];
    const float* tm = (const float*)d_in[5];
    const float* tl = (const float*)d_in[6];
    float* out = (float*)d_out;

    size_t shbytes = SMEM_FLOATS * sizeof(float);
    cudaFuncSetAttribute(tctl_kernel, cudaFuncAttributeMaxDynamicSharedMemorySize,
                         (int)shbytes);
    tctl_kernel<<<S_, THREADS, shbytes>>>(x, cf, cm, cl, tf, tm, tl, out);
}